// round 6
// baseline (speedup 1.0000x reference)
#include <cuda_runtime.h>
#include <cuda_bf16.h>
#include <cstdint>

// ---------------- problem constants ----------------
#define TT   4
#define BB   16
#define CC   512
#define NN   256
#define HID  2048
#define TBCN (TT*BB*CC*NN)     // 8,388,608

// ---------------- static scratch ----------------
__device__ float       g_xt  [64L*256*512];    // x transposed, channels-last fp32
__device__ signed char g_sx  [64L*256*512];    // spikes (x / mlp), int8
__device__ float       g_q   [64L*256*1536];   // qkv gemm out fp32 (channels-last)
__device__ signed char g_qs  [64L*256*1536];   // qkv spikes int8 (att in place in q cols)
__device__ float       g_xat [64L*256*512];    // attention block output fp32
__device__ float       g_h1  [64L*256*2048];   // fc1 out fp32
__device__ signed char g_h1s [64L*256*2048];   // fc1 spikes int8
__device__ signed char g_kvs [64*512];         // kv spikes int8
__device__ signed char g_w8h [3145728];        // weight hi plane int8: qkv|proj|fc1|fc2
__device__ signed char g_w8l [3145728];        // weight lo plane int8
__device__ float       g_ws  [4608];           // per-channel weight scale
__device__ float       g_A   [4608];           // folded BN scale
__device__ float       g_Bc  [4608];           // folded BN bias

#define W_QKV  0L
#define W_PROJ 786432L
#define W_FC1  1048576L
#define W_FC2  2097152L

// ---------------- PTX helpers (baseline ISA only) ----------------
__device__ __forceinline__ uint32_t smem_u32(const void* p) {
    uint32_t a;
    asm("{ .reg .u64 t; cvta.to.shared.u64 t, %1; cvt.u32.u64 %0, t; }" : "=r"(a) : "l"(p));
    return a;
}
__device__ __forceinline__ void cp16(uint32_t dst, const void* src) {
    asm volatile("cp.async.cg.shared.global [%0], [%1], 16;" :: "r"(dst), "l"(src));
}
#define CP_COMMIT() asm volatile("cp.async.commit_group;" ::: "memory")
#define CP_WAIT1()  asm volatile("cp.async.wait_group 1;" ::: "memory")

__device__ __forceinline__ void ldm4(uint32_t& r0, uint32_t& r1, uint32_t& r2, uint32_t& r3,
                                     uint32_t addr) {
    asm volatile("ldmatrix.sync.aligned.m8n8.x4.shared.b16 {%0,%1,%2,%3}, [%4];"
                 : "=r"(r0), "=r"(r1), "=r"(r2), "=r"(r3) : "r"(addr));
}
// int8 MMA: D(s32)[16x8] += A(s8)[16x32] * B(s8)[8x32]^T
__device__ __forceinline__ void mma16832(int* c, const uint32_t* a, uint32_t b0, uint32_t b1) {
    asm volatile("mma.sync.aligned.m16n8k32.row.col.s32.s8.s8.s32 "
                 "{%0,%1,%2,%3}, {%4,%5,%6,%7}, {%8,%9}, {%0,%1,%2,%3};"
                 : "+r"(c[0]), "+r"(c[1]), "+r"(c[2]), "+r"(c[3])
                 : "r"(a[0]), "r"(a[1]), "r"(a[2]), "r"(a[3]), "r"(b0), "r"(b1));
}

// SMEM: per stage A(128x80B) | Bhi(128x80B) | Blo(128x80B); 3 stages
#define RS    80
#define STG_A (128*RS)        // 10240
#define STAGE (3*STG_A)       // 30720
#define SMEM_TOT (3*STAGE)    // 92160

// ---------------- prep kernels ----------------
__global__ void prep_affine_kernel(const float* __restrict__ qbn, const float* __restrict__ kbn,
                                   const float* __restrict__ vbn, const float* __restrict__ pbn,
                                   const float* __restrict__ f1bn, const float* __restrict__ f2bn,
                                   const float* __restrict__ pb, const float* __restrict__ f1b,
                                   const float* __restrict__ f2b)
{
    int i = blockIdx.x * blockDim.x + threadIdx.x;
    if (i >= 4608) return;
    const float* bn; int c; int nc; float bias = 0.f;
    if (i < 1536)      { int s = i >> 9; c = i & 511; nc = CC;
                         bn = (s == 0) ? qbn : (s == 1) ? kbn : vbn; }
    else if (i < 2048) { c = i - 1536; nc = CC;  bn = pbn;  bias = pb[c]; }
    else if (i < 4096) { c = i - 2048; nc = HID; bn = f1bn; bias = f1b[c]; }
    else               { c = i - 4096; nc = CC;  bn = f2bn; bias = f2b[c]; }
    float g  = bn[c];
    float be = bn[nc + c];
    float m  = bn[2*nc + c];
    float v  = bn[3*nc + c];
    float a  = g / sqrtf(v + 1e-5f);
    g_A[i]  = a;
    g_Bc[i] = be + (bias - m) * a;
}

// per-output-channel 15-bit quantization into two int8 planes
__global__ void wquant_kernel(const float* __restrict__ q, const float* __restrict__ k,
                              const float* __restrict__ v, const float* __restrict__ pj,
                              const float* __restrict__ f1, const float* __restrict__ f2)
{
    int row = blockIdx.x;           // 0..4607 global channel
    const float* src; int K; long dst;
    if (row < 1536)      { int s = row >> 9; int r = row & 511; K = 512;
                           src = ((s == 0) ? q : (s == 1) ? k : v) + (long)r * 512;
                           dst = W_QKV + (long)row * 512; }
    else if (row < 2048) { K = 512;  src = pj + (long)(row - 1536) * 512;
                           dst = W_PROJ + (long)(row - 1536) * 512; }
    else if (row < 4096) { K = 512;  src = f1 + (long)(row - 2048) * 512;
                           dst = W_FC1 + (long)(row - 2048) * 512; }
    else                 { K = 2048; src = f2 + (long)(row - 4096) * 2048;
                           dst = W_FC2 + (long)(row - 4096) * 2048; }
    __shared__ float red[256];
    int tid = threadIdx.x;
    float m = 0.f;
    for (int i = tid; i < K; i += 256) m = fmaxf(m, fabsf(src[i]));
    red[tid] = m; __syncthreads();
    for (int o = 128; o; o >>= 1) {
        if (tid < o) red[tid] = fmaxf(red[tid], red[tid + o]);
        __syncthreads();
    }
    float mx  = red[0];
    float inv = (mx > 0.f) ? 32512.f / mx : 0.f;
    if (tid == 0) g_ws[row] = mx / 32512.f;
    for (int i = tid; i < K; i += 256) {
        int vq = __float2int_rn(src[i] * inv);
        int hi = ((vq + 32896) >> 8) - 128;     // floor((v+128)/256)
        int lo = vq - (hi << 8);                // in [-128,127]
        g_w8h[dst + i] = (signed char)hi;
        g_w8l[dst + i] = (signed char)lo;
    }
}

// fused transpose + shortcut LIF: x[t,b,c,n] -> g_xt[t,b,n,c] fp32 AND g_sx spikes int8
__global__ void xpose_lif_kernel(const float* __restrict__ x)
{
    __shared__ float t4[4][32][33];
    int b  = blockIdx.z;
    int n0 = blockIdx.x * 32, c0 = blockIdx.y * 32;
    int tx = threadIdx.x, ty = threadIdx.y;  // (32,8)
#pragma unroll
    for (int t = 0; t < TT; t++)
#pragma unroll
        for (int i = 0; i < 4; i++) {
            int c = c0 + ty + i * 8;
            t4[t][ty + i * 8][tx] = x[(((long)t * BB + b) * CC + c) * NN + n0 + tx];
        }
    __syncthreads();
#pragma unroll
    for (int i = 0; i < 4; i++) {
        int n = n0 + ty + i * 8;
        int c = c0 + tx;
        float v = 0.f;
#pragma unroll
        for (int t = 0; t < TT; t++) {
            float xv = t4[t][tx][ty + i * 8];
            long o = (((long)t * BB + b) * NN + n) * CC + c;
            g_xt[o] = xv;
            v = 0.5f * (v + xv);
            bool sp = (v >= 1.0f);
            g_sx[o] = sp ? 1 : 0;
            if (sp) v = 0.f;
        }
    }
}

// LIF: fp32 in -> int8 spikes, loop over T with stride
__global__ void lif_kernel(const float* __restrict__ in, signed char* __restrict__ out,
                           int elems, long tstride, float vth)
{
    int i = blockIdx.x * 256 + threadIdx.x;
    if (i >= elems) return;
    float v = 0.f;
#pragma unroll
    for (int t = 0; t < TT; t++) {
        float xv = in[(long)t * tstride + i];
        v = 0.5f * (v + xv);
        bool sp = (v >= vth);
        out[(long)t * tstride + i] = sp ? 1 : 0;
        if (sp) v = 0.f;
    }
}

// fused kv reduce + talking-heads LIF (vth=0.5)
__global__ void kvlif_kernel()
{
    int idx = blockIdx.x * 256 + threadIdx.x;   // 8192 = 16 b x 512 c
    int b = idx >> 9, c = idx & 511;
    float v = 0.f;
#pragma unroll
    for (int t = 0; t < TT; t++) {
        int tb = t * BB + b;
        const signed char* base = g_qs + (long)tb * NN * 1536;
        int s = 0;
#pragma unroll 4
        for (int n = 0; n < NN; n++)
            s += (int)base[(long)n * 1536 + 512 + c] * (int)base[(long)n * 1536 + 1024 + c];
        v = 0.5f * (v + (float)s);
        bool sp = (v >= 0.5f);
        g_kvs[tb * 512 + c] = sp ? 1 : 0;
        if (sp) v = 0.f;
    }
}

// blocks [0,32768): att = q&kv in place (both 0/1); blocks [32768,65536): vh output
__global__ void attvh_kernel(float* __restrict__ vh)
{
    long bi = blockIdx.x;
    if (bi < 32768) {
        long i = bi * 256 + threadIdx.x;         // over 64*256*512
        int c  = (int)(i & 511);
        int n  = (int)((i >> 9) & 255);
        int tb = (int)(i >> 17);
        long qi = ((long)tb * 256 + n) * 1536 + c;
        g_qs[qi] = (signed char)(g_qs[qi] & g_kvs[tb * 512 + c]);
    } else {
        long i = (bi - 32768) * 256 + threadIdx.x;  // over 8,388,608
        int ch = (int)(i & 63);
        int n  = (int)((i >> 6) & 255);
        int h  = (int)((i >> 14) & 7);
        int tb = (int)(i >> 17);
        vh[i] = (float)g_qs[((long)tb * 256 + n) * 1536 + 1024 + h * 64 + ch];
    }
}

// ---------------- IMMA GEMM ----------------
// 256 threads, 8 warps (2x4), warp tile 64x32, 3-stage cp.async, K-chunk 64 int8.
// D[n,c] = sum_k A[n,k]*(256*Whi+Wlo)[c,k]; epi: (Asc*Ws)[c]*Df + Bc[c] (+Res).
__global__ void __launch_bounds__(256, 1)
mma_gemm(const signed char* __restrict__ A, long a_bs, int lda,
         const signed char* __restrict__ Whi, const signed char* __restrict__ Wlo,
         long wbase, int K,
         const float* __restrict__ Asc, const float* __restrict__ Wsc,
         const float* __restrict__ Bsc,
         const float* __restrict__ Res, long res_bs,
         float* __restrict__ Out, long out_bs, int Mout, int cm)
{
    extern __shared__ char sm[];
    const uint32_t smb = smem_u32(sm);

    const int tid  = threadIdx.x;
    const int lane = tid & 31;
    const int wid  = tid >> 5;          // 8 warps
    const int wm   = wid & 1;           // 2 M-groups of 64 rows
    const int wn   = wid >> 1;          // 4 N-groups of 32 cols
    const int n0   = blockIdx.x * 128;  // spatial
    const int c0   = blockIdx.y * 128;  // channels
    const int tb   = blockIdx.z;
    const int nch  = K >> 6;

    const signed char* Ab = A + (long)tb * a_bs + (long)n0 * lda;
    const signed char* Hb = Whi + wbase + (long)c0 * K;
    const signed char* Lb = Wlo + wbase + (long)c0 * K;

    const int arow = (lane & 7) + ((lane >> 3) & 1) * 8;
    const int ac8  = (lane >> 4) * 16;
    const int brow = (lane & 7) + (lane >> 4) * 8;
    const int bc8  = ((lane >> 3) & 1) * 16;

    int acch[4][4][4], accl[4][4][4];
#pragma unroll
    for (int a_ = 0; a_ < 4; a_++)
#pragma unroll
        for (int b_ = 0; b_ < 4; b_++)
#pragma unroll
            for (int r_ = 0; r_ < 4; r_++) { acch[a_][b_][r_] = 0; accl[a_][b_][r_] = 0; }

    auto load_stage = [&](int s, int kc) {
        uint32_t base = smb + s * STAGE;
#pragma unroll
        for (int jj = 0; jj < 2; jj++) {
            int u = jj * 256 + tid;            // 0..511: 128 rows x 4 chunks
            int r = u >> 2, c16 = u & 3;
            cp16(base + r * RS + c16 * 16, Ab + (long)r * lda + kc * 64 + c16 * 16);
        }
#pragma unroll
        for (int jj = 0; jj < 2; jj++) {
            int u = jj * 256 + tid;
            int r = u >> 2, c16 = u & 3;
            cp16(base + STG_A + r * RS + c16 * 16, Hb + (long)r * K + kc * 64 + c16 * 16);
        }
#pragma unroll
        for (int jj = 0; jj < 2; jj++) {
            int u = jj * 256 + tid;
            int r = u >> 2, c16 = u & 3;
            cp16(base + 2 * STG_A + r * RS + c16 * 16, Lb + (long)r * K + kc * 64 + c16 * 16);
        }
    };

    load_stage(0, 0); CP_COMMIT();
    load_stage(1, 1); CP_COMMIT();

    for (int ch = 0; ch < nch; ch++) {
        CP_WAIT1();                  // group for chunk ch complete
        __syncthreads();             // everyone done with stage (ch+2)%3 reads from iter ch-1
        if (ch + 2 < nch) load_stage((ch + 2) % 3, ch + 2);
        CP_COMMIT();                 // unconditional -> uniform group accounting

        const uint32_t ab = smb + (ch % 3) * STAGE;
        const uint32_t hb = ab + STG_A;
        const uint32_t lb = hb + STG_A;

#pragma unroll
        for (int kt = 0; kt < 2; kt++) {
            const int ko = kt * 32;  // byte offset of k32 block
            uint32_t a[4][4];
#pragma unroll
            for (int mt = 0; mt < 4; mt++)
                ldm4(a[mt][0], a[mt][1], a[mt][2], a[mt][3],
                     ab + (wm * 64 + mt * 16 + arow) * RS + ko + ac8);

            uint32_t bh[8], bl[8];
#pragma unroll
            for (int p = 0; p < 2; p++) {
                ldm4(bh[p*4+0], bh[p*4+1], bh[p*4+2], bh[p*4+3],
                     hb + (wn * 32 + p * 16 + brow) * RS + ko + bc8);
                ldm4(bl[p*4+0], bl[p*4+1], bl[p*4+2], bl[p*4+3],
                     lb + (wn * 32 + p * 16 + brow) * RS + ko + bc8);
            }
            // all-hi then all-lo: 16 distinct accumulators per phase
#pragma unroll
            for (int g = 0; g < 4; g++) {
                int bi = (g >> 1) * 4 + (g & 1) * 2;
#pragma unroll
                for (int mt = 0; mt < 4; mt++)
                    mma16832(acch[mt][g], a[mt], bh[bi], bh[bi + 1]);
            }
#pragma unroll
            for (int g = 0; g < 4; g++) {
                int bi = (g >> 1) * 4 + (g & 1) * 2;
#pragma unroll
                for (int mt = 0; mt < 4; mt++)
                    mma16832(accl[mt][g], a[mt], bl[bi], bl[bi + 1]);
            }
        }
    }
    __syncthreads();

    // ---------------- epilogue ----------------
    if (!cm) {
#pragma unroll
        for (int mt = 0; mt < 4; mt++) {
#pragma unroll
            for (int g = 0; g < 4; g++) {
                int col = c0 + wn * 32 + g * 8 + (lane & 3) * 2;
                int row = n0 + wm * 64 + mt * 16 + (lane >> 2);
                float sA0 = Asc[col] * Wsc[col],     sB0 = Bsc[col];
                float sA1 = Asc[col + 1] * Wsc[col + 1], sB1 = Bsc[col + 1];
                float f00 = fmaf(256.f, (float)acch[mt][g][0], (float)accl[mt][g][0]);
                float f01 = fmaf(256.f, (float)acch[mt][g][1], (float)accl[mt][g][1]);
                float f10 = fmaf(256.f, (float)acch[mt][g][2], (float)accl[mt][g][2]);
                float f11 = fmaf(256.f, (float)acch[mt][g][3], (float)accl[mt][g][3]);
                float v00 = f00 * sA0 + sB0;
                float v01 = f01 * sA1 + sB1;
                float v10 = f10 * sA0 + sB0;
                float v11 = f11 * sA1 + sB1;
                if (Res) {
                    const float* r0 = Res + (long)tb * res_bs + (long)row * Mout + col;
                    float2 ra = *(const float2*)r0;
                    float2 rb = *(const float2*)(r0 + 8 * Mout);
                    v00 += ra.x; v01 += ra.y; v10 += rb.x; v11 += rb.y;
                }
                float* o0 = Out + (long)tb * out_bs + (long)row * Mout + col;
                float2 w0; w0.x = v00; w0.y = v01;
                float2 w1; w1.x = v10; w1.y = v11;
                *(float2*)o0 = w0;
                *(float2*)(o0 + 8 * Mout) = w1;
            }
        }
    } else {
        // stage through smem for coalesced channel-major stores
        float* sf = (float*)sm;
#pragma unroll
        for (int mt = 0; mt < 4; mt++) {
#pragma unroll
            for (int g = 0; g < 4; g++) {
                int cl = wn * 32 + g * 8 + (lane & 3) * 2;
                int rl = wm * 64 + mt * 16 + (lane >> 2);
                int col = c0 + cl, row = n0 + rl;
                float sA0 = Asc[col] * Wsc[col],     sB0 = Bsc[col];
                float sA1 = Asc[col + 1] * Wsc[col + 1], sB1 = Bsc[col + 1];
                float f00 = fmaf(256.f, (float)acch[mt][g][0], (float)accl[mt][g][0]);
                float f01 = fmaf(256.f, (float)acch[mt][g][1], (float)accl[mt][g][1]);
                float f10 = fmaf(256.f, (float)acch[mt][g][2], (float)accl[mt][g][2]);
                float f11 = fmaf(256.f, (float)acch[mt][g][3], (float)accl[mt][g][3]);
                float v00 = f00 * sA0 + sB0;
                float v01 = f01 * sA1 + sB1;
                float v10 = f10 * sA0 + sB0;
                float v11 = f11 * sA1 + sB1;
                const float* r0 = Res + (long)tb * res_bs + (long)row * Mout + col;
                float2 ra = *(const float2*)r0;
                float2 rb = *(const float2*)(r0 + 8 * Mout);
                v00 += ra.x; v01 += ra.y; v10 += rb.x; v11 += rb.y;
                sf[cl * 132 + rl]           = v00;
                sf[(cl + 1) * 132 + rl]     = v01;
                sf[cl * 132 + rl + 8]       = v10;
                sf[(cl + 1) * 132 + rl + 8] = v11;
            }
        }
        __syncthreads();
#pragma unroll
        for (int i = 0; i < 16; i++) {
            int c = wid * 16 + i;
            float* orow = Out + (long)tb * out_bs + (long)(c0 + c) * NN + n0;
#pragma unroll
            for (int j = 0; j < 4; j++)
                orow[lane + j * 32] = sf[c * 132 + lane + j * 32];
        }
    }
}

// ---------------- launch ----------------
extern "C" void kernel_launch(void* const* d_in, const int* in_sizes, int n_in,
                              void* d_out, int out_size)
{
    const float* x      = (const float*)d_in[0];
    const float* q_w    = (const float*)d_in[1];
    const float* k_w    = (const float*)d_in[2];
    const float* v_w    = (const float*)d_in[3];
    const float* proj_w = (const float*)d_in[4];
    const float* proj_b = (const float*)d_in[5];
    const float* fc1_w  = (const float*)d_in[6];
    const float* fc1_b  = (const float*)d_in[7];
    const float* fc2_w  = (const float*)d_in[8];
    const float* fc2_b  = (const float*)d_in[9];
    const float* q_bn   = (const float*)d_in[10];
    const float* k_bn   = (const float*)d_in[11];
    const float* v_bn   = (const float*)d_in[12];
    const float* proj_bn= (const float*)d_in[13];
    const float* fc1_bn = (const float*)d_in[14];
    const float* fc2_bn = (const float*)d_in[15];
    float* out = (float*)d_out;

    cudaFuncSetAttribute(mma_gemm, cudaFuncAttributeMaxDynamicSharedMemorySize, SMEM_TOT);

    float *p_xt, *p_q, *p_xat, *p_h1, *p_A, *p_Bc, *p_ws;
    signed char *p_sx, *p_qs, *p_h1s, *p_w8h, *p_w8l;
    cudaGetSymbolAddress((void**)&p_xt,  g_xt);
    cudaGetSymbolAddress((void**)&p_sx,  g_sx);
    cudaGetSymbolAddress((void**)&p_q,   g_q);
    cudaGetSymbolAddress((void**)&p_qs,  g_qs);
    cudaGetSymbolAddress((void**)&p_xat, g_xat);
    cudaGetSymbolAddress((void**)&p_h1,  g_h1);
    cudaGetSymbolAddress((void**)&p_h1s, g_h1s);
    cudaGetSymbolAddress((void**)&p_w8h, g_w8h);
    cudaGetSymbolAddress((void**)&p_w8l, g_w8l);
    cudaGetSymbolAddress((void**)&p_ws,  g_ws);
    cudaGetSymbolAddress((void**)&p_A,   g_A);
    cudaGetSymbolAddress((void**)&p_Bc,  g_Bc);

    prep_affine_kernel<<<18, 256>>>(q_bn, k_bn, v_bn, proj_bn, fc1_bn, fc2_bn,
                                    proj_b, fc1_b, fc2_b);
    wquant_kernel<<<4608, 256>>>(q_w, k_w, v_w, proj_w, fc1_w, fc2_w);
    xpose_lif_kernel<<<dim3(8, 16, 16), dim3(32, 8)>>>(x);

    // qkv GEMM (Mout=1536 stacked)
    mma_gemm<<<dim3(2, 12, 64), 256, SMEM_TOT>>>(p_sx, (long)NN*CC, CC,
                                                 p_w8h, p_w8l, W_QKV, CC,
                                                 p_A, p_ws, p_Bc, nullptr, 0,
                                                 p_q, (long)NN*1536, 1536, 0);
    lif_kernel<<<24576, 256>>>(p_q, p_qs, BB*NN*1536, (long)BB*NN*1536, 1.0f);

    kvlif_kernel<<<32, 256>>>();
    attvh_kernel<<<65536, 256>>>(out + (long)TBCN);

    // proj GEMM + BN + identity(x)
    mma_gemm<<<dim3(2, 4, 64), 256, SMEM_TOT>>>(p_qs, (long)NN*1536, 1536,
                                                p_w8h, p_w8l, W_PROJ, CC,
                                                p_A + 1536, p_ws + 1536, p_Bc + 1536,
                                                p_xt, (long)NN*CC,
                                                p_xat, (long)NN*CC, CC, 0);
    lif_kernel<<<8192, 256>>>(p_xat, p_sx, BB*NN*CC, (long)BB*NN*CC, 1.0f);

    // fc1 GEMM
    mma_gemm<<<dim3(2, 16, 64), 256, SMEM_TOT>>>(p_sx, (long)NN*CC, CC,
                                                 p_w8h, p_w8l, W_FC1, CC,
                                                 p_A + 2048, p_ws + 2048, p_Bc + 2048,
                                                 nullptr, 0,
                                                 p_h1, (long)NN*HID, HID, 0);
    lif_kernel<<<32768, 256>>>(p_h1, p_h1s, BB*NN*HID, (long)BB*NN*HID, 1.0f);

    // fc2 GEMM + BN + idm(x_attn) -> d_out (channel-major, smem-staged)
    mma_gemm<<<dim3(2, 4, 64), 256, SMEM_TOT>>>(p_h1s, (long)NN*HID, HID,
                                                p_w8h, p_w8l, W_FC2, HID,
                                                p_A + 4096, p_ws + 4096, p_Bc + 4096,
                                                p_xat, (long)NN*CC,
                                                out, (long)CC*NN, CC, 1);
}

// round 7
// speedup vs baseline: 2.4482x; 2.4482x over previous
#include <cuda_runtime.h>
#include <cuda_bf16.h>
#include <cstdint>

// ---------------- problem constants ----------------
#define TT   4
#define BB   16
#define CC   512
#define NN   256
#define HID  2048
#define TBCN (TT*BB*CC*NN)     // 8,388,608

// ---------------- static scratch ----------------
__device__ float         g_xt  [64L*256*512];    // x transposed, channels-last fp32
__device__ __nv_bfloat16 g_sx  [64L*256*512];    // spikes (x / mlp), bf16
__device__ float         g_q   [64L*256*1536];   // qkv gemm out fp32 (channels-last)
__device__ __nv_bfloat16 g_qs  [64L*256*1536];   // qkv spikes bf16 (att in place in q cols)
__device__ float         g_xat [64L*256*512];    // attention block output fp32
__device__ float         g_h1  [64L*256*2048];   // fc1 out fp32
__device__ __nv_bfloat16 g_h1s [64L*256*2048];   // fc1 spikes bf16
__device__ __nv_bfloat16 g_kvs [64*512];         // kv spikes bf16
__device__ __nv_bfloat16 g_whi [3145728];        // weights hi bf16: qkv|proj|fc1|fc2
__device__ __nv_bfloat16 g_wlo [3145728];        // weights lo bf16
__device__ float         g_A   [4608];           // folded BN scale
__device__ float         g_Bc  [4608];           // folded BN bias

#define W_QKV  0L
#define W_PROJ 786432L
#define W_FC1  1048576L
#define W_FC2  2097152L

#define BF1 ((unsigned short)0x3F80)

// ---------------- PTX helpers (baseline ISA only) ----------------
__device__ __forceinline__ uint32_t smem_u32(const void* p) {
    uint32_t a;
    asm("{ .reg .u64 t; cvta.to.shared.u64 t, %1; cvt.u32.u64 %0, t; }" : "=r"(a) : "l"(p));
    return a;
}
__device__ __forceinline__ void cp16(uint32_t dst, const void* src) {
    asm volatile("cp.async.cg.shared.global [%0], [%1], 16;" :: "r"(dst), "l"(src));
}
#define CP_COMMIT() asm volatile("cp.async.commit_group;" ::: "memory")
#define CP_WAIT0()  asm volatile("cp.async.wait_group 0;" ::: "memory")

__device__ __forceinline__ void ldm4(uint32_t& r0, uint32_t& r1, uint32_t& r2, uint32_t& r3,
                                     uint32_t addr) {
    asm volatile("ldmatrix.sync.aligned.m8n8.x4.shared.b16 {%0,%1,%2,%3}, [%4];"
                 : "=r"(r0), "=r"(r1), "=r"(r2), "=r"(r3) : "r"(addr));
}
__device__ __forceinline__ void mma16816(float* c, const uint32_t* a, uint32_t b0, uint32_t b1) {
    asm volatile("mma.sync.aligned.m16n8k16.row.col.f32.bf16.bf16.f32 "
                 "{%0,%1,%2,%3}, {%4,%5,%6,%7}, {%8,%9}, {%0,%1,%2,%3};"
                 : "+f"(c[0]), "+f"(c[1]), "+f"(c[2]), "+f"(c[3])
                 : "r"(a[0]), "r"(a[1]), "r"(a[2]), "r"(a[3]), "r"(b0), "r"(b1));
}

// SMEM: per stage A(128x144B) | Bhi(128x144B) | Blo(128x144B); 2 stages
#define RS    144
#define STG_A (128*RS)        // 18432
#define STAGE (3*STG_A)       // 55296
#define SMEM_TOT (2*STAGE)    // 110592  (x2 CTAs/SM = 221184 <= 228KB)

// ---------------- prep kernels ----------------
__global__ void prep_affine_kernel(const float* __restrict__ qbn, const float* __restrict__ kbn,
                                   const float* __restrict__ vbn, const float* __restrict__ pbn,
                                   const float* __restrict__ f1bn, const float* __restrict__ f2bn,
                                   const float* __restrict__ pb, const float* __restrict__ f1b,
                                   const float* __restrict__ f2b)
{
    int i = blockIdx.x * blockDim.x + threadIdx.x;
    if (i >= 4608) return;
    const float* bn; int c; int nc; float bias = 0.f;
    if (i < 1536)      { int s = i >> 9; c = i & 511; nc = CC;
                         bn = (s == 0) ? qbn : (s == 1) ? kbn : vbn; }
    else if (i < 2048) { c = i - 1536; nc = CC;  bn = pbn;  bias = pb[c]; }
    else if (i < 4096) { c = i - 2048; nc = HID; bn = f1bn; bias = f1b[c]; }
    else               { c = i - 4096; nc = CC;  bn = f2bn; bias = f2b[c]; }
    float g  = bn[c];
    float be = bn[nc + c];
    float m  = bn[2*nc + c];
    float v  = bn[3*nc + c];
    float a  = g / sqrtf(v + 1e-5f);
    g_A[i]  = a;
    g_Bc[i] = be + (bias - m) * a;
}

__global__ void wconv_kernel(const float* __restrict__ q, const float* __restrict__ k,
                             const float* __restrict__ v, const float* __restrict__ pj,
                             const float* __restrict__ f1, const float* __restrict__ f2)
{
    long i = (long)blockIdx.x * 256 + threadIdx.x;
    if (i >= 3145728L) return;
    float w;
    if (i < 786432L)       { long s = i / 262144L, r = i % 262144L;
                             w = (s == 0) ? q[r] : (s == 1) ? k[r] : v[r]; }
    else if (i < 1048576L) w = pj[i - 786432L];
    else if (i < 2097152L) w = f1[i - 1048576L];
    else                   w = f2[i - 2097152L];
    __nv_bfloat16 h = __float2bfloat16(w);
    g_whi[i] = h;
    g_wlo[i] = __float2bfloat16(w - __bfloat162float(h));
}

// fused transpose + shortcut LIF: x[t,b,c,n] -> g_xt[t,b,n,c] fp32 AND g_sx spikes bf16
__global__ void xpose_lif_kernel(const float* __restrict__ x)
{
    __shared__ float t4[4][32][33];
    int b  = blockIdx.z;
    int n0 = blockIdx.x * 32, c0 = blockIdx.y * 32;
    int tx = threadIdx.x, ty = threadIdx.y;  // (32,8)
#pragma unroll
    for (int t = 0; t < TT; t++)
#pragma unroll
        for (int i = 0; i < 4; i++) {
            int c = c0 + ty + i * 8;
            t4[t][ty + i * 8][tx] = x[(((long)t * BB + b) * CC + c) * NN + n0 + tx];
        }
    __syncthreads();
#pragma unroll
    for (int i = 0; i < 4; i++) {
        int n = n0 + ty + i * 8;
        int c = c0 + tx;
        float v = 0.f;
#pragma unroll
        for (int t = 0; t < TT; t++) {
            float xv = t4[t][tx][ty + i * 8];
            long o = (((long)t * BB + b) * NN + n) * CC + c;
            g_xt[o] = xv;
            v = 0.5f * (v + xv);
            bool sp = (v >= 1.0f);
            g_sx[o] = __float2bfloat16(sp ? 1.f : 0.f);
            if (sp) v = 0.f;
        }
    }
}

// vectorized LIF: 4 elems/thread, fp32 in -> bf16 spikes out
__global__ void lif4_kernel(const float4* __restrict__ in, ushort4* __restrict__ out,
                            int n4, long t4stride, float vth)
{
    int i = blockIdx.x * 256 + threadIdx.x;
    if (i >= n4) return;
    float vx = 0.f, vy = 0.f, vz = 0.f, vw = 0.f;
#pragma unroll
    for (int t = 0; t < TT; t++) {
        float4 xv = in[(long)t * t4stride + i];
        ushort4 s;
        vx = 0.5f * (vx + xv.x); s.x = (vx >= vth) ? BF1 : 0; if (vx >= vth) vx = 0.f;
        vy = 0.5f * (vy + xv.y); s.y = (vy >= vth) ? BF1 : 0; if (vy >= vth) vy = 0.f;
        vz = 0.5f * (vz + xv.z); s.z = (vz >= vth) ? BF1 : 0; if (vz >= vth) vz = 0.f;
        vw = 0.5f * (vw + xv.w); s.w = (vw >= vth) ? BF1 : 0; if (vw >= vth) vw = 0.f;
        out[(long)t * t4stride + i] = s;
    }
}

// fused kv reduce + talking-heads LIF (vth=0.5); spikes are 0x0000/0x3F80 -> bitwise AND count
__global__ void kvlif_kernel()
{
    int idx = blockIdx.x * 256 + threadIdx.x;   // 8192 = 16 b x 512 c
    int b = idx >> 9, c = idx & 511;
    const unsigned short* qs = (const unsigned short*)g_qs;
    float v = 0.f;
#pragma unroll
    for (int t = 0; t < TT; t++) {
        int tb = t * BB + b;
        const unsigned short* base = qs + (long)tb * NN * 1536;
        int s = 0;
#pragma unroll 4
        for (int n = 0; n < NN; n++)
            s += (base[(long)n * 1536 + 512 + c] & base[(long)n * 1536 + 1024 + c]) ? 1 : 0;
        v = 0.5f * (v + (float)s);
        bool sp = (v >= 0.5f);
        g_kvs[tb * 512 + c] = __float2bfloat16(sp ? 1.f : 0.f);
        if (sp) v = 0.f;
    }
}

// blocks [0,8192): att = q&kv (bitwise, 4 lanes); blocks [8192,16384): vh output
__global__ void attvh_kernel(float4* __restrict__ vh)
{
    int bi = blockIdx.x;
    const uint2* qs2 = (const uint2*)g_qs;
    if (bi < 8192) {
        long i = (long)bi * 256 + threadIdx.x;      // quads over 64*256*512
        int c4 = (int)(i & 127);
        int n  = (int)((i >> 7) & 255);
        int tb = (int)(i >> 15);
        long qq = (((long)tb * 256 + n) * 1536 + c4 * 4) >> 2;   // uint2 index (4 bf16)
        uint2 q = ((uint2*)g_qs)[qq];
        uint2 kv = ((const uint2*)g_kvs)[((long)tb * 512 + c4 * 4) >> 2];
        q.x &= kv.x; q.y &= kv.y;
        ((uint2*)g_qs)[qq] = q;
    } else {
        long i = (long)(bi - 8192) * 256 + threadIdx.x;  // quads over 8,388,608
        int ch4 = (int)(i & 15);
        int n   = (int)((i >> 4) & 255);
        int h   = (int)((i >> 12) & 7);
        int tb  = (int)(i >> 15);
        uint2 s = qs2[(((long)tb * 256 + n) * 1536 + 1024 + h * 64 + ch4 * 4) >> 2];
        float4 o;
        o.x = (s.x & 0xFFFFu)  ? 1.f : 0.f;
        o.y = (s.x >> 16)      ? 1.f : 0.f;
        o.z = (s.y & 0xFFFFu)  ? 1.f : 0.f;
        o.w = (s.y >> 16)      ? 1.f : 0.f;
        vh[i] = o;
    }
}

// ---------------- HMMA GEMM ----------------
// 256 threads, 8 warps (2x4), warp tile 64x32, 2-stage cp.async, 1 sync/chunk, 2 CTAs/SM.
__global__ void __launch_bounds__(256, 2)
mma_gemm(const __nv_bfloat16* __restrict__ A, long a_bs, int lda,
         const __nv_bfloat16* __restrict__ Whi, const __nv_bfloat16* __restrict__ Wlo,
         long wbase, int K,
         const float* __restrict__ Asc, const float* __restrict__ Bsc,
         const float* __restrict__ Res, long res_bs,
         float* __restrict__ Out, long out_bs, int Mout, int cm)
{
    extern __shared__ char sm[];
    const uint32_t smb = smem_u32(sm);

    const int tid  = threadIdx.x;
    const int lane = tid & 31;
    const int wid  = tid >> 5;          // 8 warps
    const int wm   = wid & 1;           // 2 M-groups of 64 rows
    const int wn   = wid >> 1;          // 4 N-groups of 32 cols
    const int n0   = blockIdx.x * 128;  // spatial
    const int c0   = blockIdx.y * 128;  // channels
    const int tb   = blockIdx.z;
    const int nch  = K >> 6;

    const __nv_bfloat16* Ab = A + (long)tb * a_bs + (long)n0 * lda;
    const __nv_bfloat16* Hb = Whi + wbase + (long)c0 * K;
    const __nv_bfloat16* Lb = Wlo + wbase + (long)c0 * K;

    const int arow = (lane & 7) + ((lane >> 3) & 1) * 8;
    const int ac8  = (lane >> 4) * 16;
    const int brow = (lane & 7) + (lane >> 4) * 8;
    const int bc8  = ((lane >> 3) & 1) * 16;

    float acc[4][4][4];
#pragma unroll
    for (int a_ = 0; a_ < 4; a_++)
#pragma unroll
        for (int b_ = 0; b_ < 4; b_++)
#pragma unroll
            for (int r_ = 0; r_ < 4; r_++) acc[a_][b_][r_] = 0.f;

    auto load_stage = [&](int s, int kc) {
        uint32_t base = smb + s * STAGE;
#pragma unroll
        for (int jj = 0; jj < 4; jj++) {
            int u = jj * 256 + tid;            // 0..1023
            int r = u >> 3, c16 = u & 7;
            cp16(base + r * RS + c16 * 16, Ab + (long)r * lda + kc * 64 + c16 * 8);
        }
#pragma unroll
        for (int jj = 0; jj < 4; jj++) {
            int u = jj * 256 + tid;
            int r = u >> 3, c16 = u & 7;
            cp16(base + STG_A + r * RS + c16 * 16, Hb + (long)r * K + kc * 64 + c16 * 8);
        }
#pragma unroll
        for (int jj = 0; jj < 4; jj++) {
            int u = jj * 256 + tid;
            int r = u >> 3, c16 = u & 7;
            cp16(base + 2 * STG_A + r * RS + c16 * 16, Lb + (long)r * K + kc * 64 + c16 * 8);
        }
    };

    load_stage(0, 0);
    CP_COMMIT();

    for (int ch = 0; ch < nch; ch++) {
        CP_WAIT0();            // this thread's loads for chunk ch complete
        __syncthreads();       // all threads' loads done AND iter ch-1 compute done
        if (ch + 1 < nch) { load_stage((ch + 1) & 1, ch + 1); CP_COMMIT(); }

        const int s = ch & 1;
        const uint32_t ab = smb + s * STAGE;
        const uint32_t hb = ab + STG_A;
        const uint32_t lb = hb + STG_A;

#pragma unroll
        for (int kt = 0; kt < 4; kt++) {
            const int ko = kt * 32;  // byte offset of k16 block
            uint32_t a[4][4];
#pragma unroll
            for (int mt = 0; mt < 4; mt++)
                ldm4(a[mt][0], a[mt][1], a[mt][2], a[mt][3],
                     ab + (wm * 64 + mt * 16 + arow) * RS + ko + ac8);

            uint32_t bh[8], bl[8];
#pragma unroll
            for (int p = 0; p < 2; p++) {
                ldm4(bh[p*4+0], bh[p*4+1], bh[p*4+2], bh[p*4+3],
                     hb + (wn * 32 + p * 16 + brow) * RS + ko + bc8);
                ldm4(bl[p*4+0], bl[p*4+1], bl[p*4+2], bl[p*4+3],
                     lb + (wn * 32 + p * 16 + brow) * RS + ko + bc8);
            }
            // all-hi then all-lo: 16 distinct accumulators per phase, no RAW stalls
#pragma unroll
            for (int g = 0; g < 4; g++) {
                int bi = (g >> 1) * 4 + (g & 1) * 2;
#pragma unroll
                for (int mt = 0; mt < 4; mt++)
                    mma16816(acc[mt][g], a[mt], bh[bi], bh[bi + 1]);
            }
#pragma unroll
            for (int g = 0; g < 4; g++) {
                int bi = (g >> 1) * 4 + (g & 1) * 2;
#pragma unroll
                for (int mt = 0; mt < 4; mt++)
                    mma16816(acc[mt][g], a[mt], bl[bi], bl[bi + 1]);
            }
        }
    }
    __syncthreads();

    // ---------------- epilogue ----------------
    if (!cm) {
#pragma unroll
        for (int mt = 0; mt < 4; mt++) {
#pragma unroll
            for (int g = 0; g < 4; g++) {
                int col = c0 + wn * 32 + g * 8 + (lane & 3) * 2;
                int row = n0 + wm * 64 + mt * 16 + (lane >> 2);
                float sA0 = Asc[col], sA1 = Asc[col + 1];
                float sB0 = Bsc[col], sB1 = Bsc[col + 1];
                float v00 = acc[mt][g][0] * sA0 + sB0;
                float v01 = acc[mt][g][1] * sA1 + sB1;
                float v10 = acc[mt][g][2] * sA0 + sB0;
                float v11 = acc[mt][g][3] * sA1 + sB1;
                if (Res) {
                    const float* r0 = Res + (long)tb * res_bs + (long)row * Mout + col;
                    float2 ra = *(const float2*)r0;
                    float2 rb = *(const float2*)(r0 + 8 * Mout);
                    v00 += ra.x; v01 += ra.y; v10 += rb.x; v11 += rb.y;
                }
                float* o0 = Out + (long)tb * out_bs + (long)row * Mout + col;
                float2 w0; w0.x = v00; w0.y = v01;
                float2 w1; w1.x = v10; w1.y = v11;
                *(float2*)o0 = w0;
                *(float2*)(o0 + 8 * Mout) = w1;
            }
        }
    } else {
        // stage through smem for coalesced channel-major stores
        float* sf = (float*)sm;
#pragma unroll
        for (int mt = 0; mt < 4; mt++) {
#pragma unroll
            for (int g = 0; g < 4; g++) {
                int cl = wn * 32 + g * 8 + (lane & 3) * 2;
                int rl = wm * 64 + mt * 16 + (lane >> 2);
                int col = c0 + cl, row = n0 + rl;
                float sA0 = Asc[col], sA1 = Asc[col + 1];
                float sB0 = Bsc[col], sB1 = Bsc[col + 1];
                float v00 = acc[mt][g][0] * sA0 + sB0;
                float v01 = acc[mt][g][1] * sA1 + sB1;
                float v10 = acc[mt][g][2] * sA0 + sB0;
                float v11 = acc[mt][g][3] * sA1 + sB1;
                const float* r0 = Res + (long)tb * res_bs + (long)row * Mout + col;
                float2 ra = *(const float2*)r0;
                float2 rb = *(const float2*)(r0 + 8 * Mout);
                v00 += ra.x; v01 += ra.y; v10 += rb.x; v11 += rb.y;
                sf[cl * 132 + rl]           = v00;
                sf[(cl + 1) * 132 + rl]     = v01;
                sf[cl * 132 + rl + 8]       = v10;
                sf[(cl + 1) * 132 + rl + 8] = v11;
            }
        }
        __syncthreads();
#pragma unroll
        for (int i = 0; i < 16; i++) {
            int c = wid * 16 + i;
            float* orow = Out + (long)tb * out_bs + (long)(c0 + c) * NN + n0;
#pragma unroll
            for (int j = 0; j < 4; j++)
                orow[lane + j * 32] = sf[c * 132 + lane + j * 32];
        }
    }
}

// ---------------- launch ----------------
extern "C" void kernel_launch(void* const* d_in, const int* in_sizes, int n_in,
                              void* d_out, int out_size)
{
    const float* x      = (const float*)d_in[0];
    const float* q_w    = (const float*)d_in[1];
    const float* k_w    = (const float*)d_in[2];
    const float* v_w    = (const float*)d_in[3];
    const float* proj_w = (const float*)d_in[4];
    const float* proj_b = (const float*)d_in[5];
    const float* fc1_w  = (const float*)d_in[6];
    const float* fc1_b  = (const float*)d_in[7];
    const float* fc2_w  = (const float*)d_in[8];
    const float* fc2_b  = (const float*)d_in[9];
    const float* q_bn   = (const float*)d_in[10];
    const float* k_bn   = (const float*)d_in[11];
    const float* v_bn   = (const float*)d_in[12];
    const float* proj_bn= (const float*)d_in[13];
    const float* fc1_bn = (const float*)d_in[14];
    const float* fc2_bn = (const float*)d_in[15];
    float* out = (float*)d_out;

    cudaFuncSetAttribute(mma_gemm, cudaFuncAttributeMaxDynamicSharedMemorySize, SMEM_TOT);

    float *p_xt, *p_q, *p_xat, *p_h1, *p_A, *p_Bc;
    __nv_bfloat16 *p_sx, *p_qs, *p_h1s, *p_whi, *p_wlo;
    cudaGetSymbolAddress((void**)&p_xt,  g_xt);
    cudaGetSymbolAddress((void**)&p_sx,  g_sx);
    cudaGetSymbolAddress((void**)&p_q,   g_q);
    cudaGetSymbolAddress((void**)&p_qs,  g_qs);
    cudaGetSymbolAddress((void**)&p_xat, g_xat);
    cudaGetSymbolAddress((void**)&p_h1,  g_h1);
    cudaGetSymbolAddress((void**)&p_h1s, g_h1s);
    cudaGetSymbolAddress((void**)&p_whi, g_whi);
    cudaGetSymbolAddress((void**)&p_wlo, g_wlo);
    cudaGetSymbolAddress((void**)&p_A,   g_A);
    cudaGetSymbolAddress((void**)&p_Bc,  g_Bc);

    prep_affine_kernel<<<18, 256>>>(q_bn, k_bn, v_bn, proj_bn, fc1_bn, fc2_bn,
                                    proj_b, fc1_b, fc2_b);
    wconv_kernel<<<12288, 256>>>(q_w, k_w, v_w, proj_w, fc1_w, fc2_w);
    xpose_lif_kernel<<<dim3(8, 16, 16), dim3(32, 8)>>>(x);

    // qkv GEMM (Mout=1536 stacked)
    mma_gemm<<<dim3(2, 12, 64), 256, SMEM_TOT>>>(p_sx, (long)NN*CC, CC,
                                                 p_whi, p_wlo, W_QKV, CC,
                                                 p_A, p_Bc, nullptr, 0,
                                                 p_q, (long)NN*1536, 1536, 0);
    // LIF on qkv (4 elems/thread)
    lif4_kernel<<<6144, 256>>>((const float4*)p_q, (ushort4*)p_qs,
                               BB*NN*1536/4, (long)BB*NN*1536/4, 1.0f);

    kvlif_kernel<<<32, 256>>>();
    attvh_kernel<<<16384, 256>>>((float4*)(out + (long)TBCN));

    // proj GEMM + BN + identity(x)
    mma_gemm<<<dim3(2, 4, 64), 256, SMEM_TOT>>>(p_qs, (long)NN*1536, 1536,
                                                p_whi, p_wlo, W_PROJ, CC,
                                                p_A + 1536, p_Bc + 1536, p_xt, (long)NN*CC,
                                                p_xat, (long)NN*CC, CC, 0);
    lif4_kernel<<<2048, 256>>>((const float4*)p_xat, (ushort4*)p_sx,
                               BB*NN*CC/4, (long)BB*NN*CC/4, 1.0f);

    // fc1 GEMM
    mma_gemm<<<dim3(2, 16, 64), 256, SMEM_TOT>>>(p_sx, (long)NN*CC, CC,
                                                 p_whi, p_wlo, W_FC1, CC,
                                                 p_A + 2048, p_Bc + 2048, nullptr, 0,
                                                 p_h1, (long)NN*HID, HID, 0);
    lif4_kernel<<<8192, 256>>>((const float4*)p_h1, (ushort4*)p_h1s,
                               BB*NN*HID/4, (long)BB*NN*HID/4, 1.0f);

    // fc2 GEMM + BN + idm(x_attn) -> d_out (channel-major, smem-staged)
    mma_gemm<<<dim3(2, 4, 64), 256, SMEM_TOT>>>(p_h1s, (long)NN*HID, HID,
                                                p_whi, p_wlo, W_FC2, HID,
                                                p_A + 4096, p_Bc + 4096, p_xat, (long)NN*CC,
                                                out, (long)CC*NN, CC, 1);
}

// round 8
// speedup vs baseline: 2.6663x; 1.0891x over previous
#include <cuda_runtime.h>
#include <cuda_bf16.h>
#include <cstdint>

// ---------------- problem constants ----------------
#define TT   4
#define BB   16
#define CC   512
#define NN   256
#define HID  2048
#define TBCN (TT*BB*CC*NN)     // 8,388,608

// ---------------- static scratch ----------------
__device__ float         g_xt  [64L*256*512];    // x transposed, channels-last fp32
__device__ __nv_bfloat16 g_sx  [64L*256*512];    // spikes (x / mlp), bf16
__device__ float         g_q   [64L*256*1536];   // qkv gemm out fp32 (channels-last)
__device__ __nv_bfloat16 g_qs  [64L*256*1536];   // qkv spikes bf16 (att in place in q cols)
__device__ float         g_xat [64L*256*512];    // attention block output fp32
__device__ float         g_h1  [64L*256*2048];   // fc1 out fp32
__device__ __nv_bfloat16 g_h1s [64L*256*2048];   // fc1 spikes bf16
__device__ __nv_bfloat16 g_kvs [64*512];         // kv spikes bf16
__device__ int           g_kvcnt[64*512];        // kv AND-counts (int, exact)
__device__ __nv_bfloat16 g_whi [3145728];        // weights hi bf16: qkv|proj|fc1|fc2
__device__ __nv_bfloat16 g_wlo [3145728];        // weights lo bf16
__device__ float         g_A   [4608];           // folded BN scale
__device__ float         g_Bc  [4608];           // folded BN bias

#define W_QKV  0L
#define W_PROJ 786432L
#define W_FC1  1048576L
#define W_FC2  2097152L

#define BF1 ((unsigned short)0x3F80)

// ---------------- PTX helpers (baseline ISA only) ----------------
__device__ __forceinline__ uint32_t smem_u32(const void* p) {
    uint32_t a;
    asm("{ .reg .u64 t; cvta.to.shared.u64 t, %1; cvt.u32.u64 %0, t; }" : "=r"(a) : "l"(p));
    return a;
}
__device__ __forceinline__ void cp16(uint32_t dst, const void* src) {
    asm volatile("cp.async.cg.shared.global [%0], [%1], 16;" :: "r"(dst), "l"(src));
}
#define CP_COMMIT() asm volatile("cp.async.commit_group;" ::: "memory")
#define CP_WAIT1()  asm volatile("cp.async.wait_group 1;" ::: "memory")
#define CP_WAIT0()  asm volatile("cp.async.wait_group 0;" ::: "memory")

__device__ __forceinline__ void ldm4(uint32_t& r0, uint32_t& r1, uint32_t& r2, uint32_t& r3,
                                     uint32_t addr) {
    asm volatile("ldmatrix.sync.aligned.m8n8.x4.shared.b16 {%0,%1,%2,%3}, [%4];"
                 : "=r"(r0), "=r"(r1), "=r"(r2), "=r"(r3) : "r"(addr));
}
__device__ __forceinline__ void mma16816(float* c, const uint32_t* a, uint32_t b0, uint32_t b1) {
    asm volatile("mma.sync.aligned.m16n8k16.row.col.f32.bf16.bf16.f32 "
                 "{%0,%1,%2,%3}, {%4,%5,%6,%7}, {%8,%9}, {%0,%1,%2,%3};"
                 : "+f"(c[0]), "+f"(c[1]), "+f"(c[2]), "+f"(c[3])
                 : "r"(a[0]), "r"(a[1]), "r"(a[2]), "r"(a[3]), "r"(b0), "r"(b1));
}

// SMEM: per stage A(128x80B) | Bhi(128x80B) | Blo(128x80B); 3 stages; K-chunk = 32 bf16
#define RS    80
#define STG_A (128*RS)        // 10240
#define STAGE (3*STG_A)       // 30720
#define SMEM_TOT (3*STAGE)    // 92160  (x2 CTAs/SM = 184320 <= 228KB)

// ---------------- prep kernels ----------------
__global__ void prep_affine_kernel(const float* __restrict__ qbn, const float* __restrict__ kbn,
                                   const float* __restrict__ vbn, const float* __restrict__ pbn,
                                   const float* __restrict__ f1bn, const float* __restrict__ f2bn,
                                   const float* __restrict__ pb, const float* __restrict__ f1b,
                                   const float* __restrict__ f2b)
{
    int i = blockIdx.x * blockDim.x + threadIdx.x;
    if (i >= 4608) return;
    const float* bn; int c; int nc; float bias = 0.f;
    if (i < 1536)      { int s = i >> 9; c = i & 511; nc = CC;
                         bn = (s == 0) ? qbn : (s == 1) ? kbn : vbn; }
    else if (i < 2048) { c = i - 1536; nc = CC;  bn = pbn;  bias = pb[c]; }
    else if (i < 4096) { c = i - 2048; nc = HID; bn = f1bn; bias = f1b[c]; }
    else               { c = i - 4096; nc = CC;  bn = f2bn; bias = f2b[c]; }
    float g  = bn[c];
    float be = bn[nc + c];
    float m  = bn[2*nc + c];
    float v  = bn[3*nc + c];
    float a  = g / sqrtf(v + 1e-5f);
    g_A[i]  = a;
    g_Bc[i] = be + (bias - m) * a;
}

__global__ void wconv_kernel(const float* __restrict__ q, const float* __restrict__ k,
                             const float* __restrict__ v, const float* __restrict__ pj,
                             const float* __restrict__ f1, const float* __restrict__ f2)
{
    long i = (long)blockIdx.x * 256 + threadIdx.x;
    if (i >= 3145728L) return;
    float w;
    if (i < 786432L)       { long s = i / 262144L, r = i % 262144L;
                             w = (s == 0) ? q[r] : (s == 1) ? k[r] : v[r]; }
    else if (i < 1048576L) w = pj[i - 786432L];
    else if (i < 2097152L) w = f1[i - 1048576L];
    else                   w = f2[i - 2097152L];
    __nv_bfloat16 h = __float2bfloat16(w);
    g_whi[i] = h;
    g_wlo[i] = __float2bfloat16(w - __bfloat162float(h));
}

// fused transpose + shortcut LIF: x[t,b,c,n] -> g_xt[t,b,n,c] fp32 AND g_sx spikes bf16
__global__ void xpose_lif_kernel(const float* __restrict__ x)
{
    __shared__ float t4[4][32][33];
    int b  = blockIdx.z;
    int n0 = blockIdx.x * 32, c0 = blockIdx.y * 32;
    int tx = threadIdx.x, ty = threadIdx.y;  // (32,8)
#pragma unroll
    for (int t = 0; t < TT; t++)
#pragma unroll
        for (int i = 0; i < 4; i++) {
            int c = c0 + ty + i * 8;
            t4[t][ty + i * 8][tx] = x[(((long)t * BB + b) * CC + c) * NN + n0 + tx];
        }
    __syncthreads();
#pragma unroll
    for (int i = 0; i < 4; i++) {
        int n = n0 + ty + i * 8;
        int c = c0 + tx;
        float v = 0.f;
#pragma unroll
        for (int t = 0; t < TT; t++) {
            float xv = t4[t][tx][ty + i * 8];
            long o = (((long)t * BB + b) * NN + n) * CC + c;
            g_xt[o] = xv;
            v = 0.5f * (v + xv);
            bool sp = (v >= 1.0f);
            g_sx[o] = __float2bfloat16(sp ? 1.f : 0.f);
            if (sp) v = 0.f;
        }
    }
}

// vectorized LIF: 4 elems/thread, fp32 in -> bf16 spikes out
__global__ void lif4_kernel(const float4* __restrict__ in, ushort4* __restrict__ out,
                            int n4, long t4stride, float vth)
{
    int i = blockIdx.x * 256 + threadIdx.x;
    if (i >= n4) return;
    float vx = 0.f, vy = 0.f, vz = 0.f, vw = 0.f;
#pragma unroll
    for (int t = 0; t < TT; t++) {
        float4 xv = in[(long)t * t4stride + i];
        ushort4 s;
        vx = 0.5f * (vx + xv.x); s.x = (vx >= vth) ? BF1 : 0; if (vx >= vth) vx = 0.f;
        vy = 0.5f * (vy + xv.y); s.y = (vy >= vth) ? BF1 : 0; if (vy >= vth) vy = 0.f;
        vz = 0.5f * (vz + xv.z); s.z = (vz >= vth) ? BF1 : 0; if (vz >= vth) vz = 0.f;
        vw = 0.5f * (vw + xv.w); s.w = (vw >= vth) ? BF1 : 0; if (vw >= vth) vw = 0.f;
        out[(long)t * t4stride + i] = s;
    }
}

// coalesced kv AND-count: block = (tb, ngroup of 64 rows); thread owns 2 channels.
// spikes are 0x0000/0x3F80 so (k & v) != 0 per 16-bit lane iff both spiked.
__global__ void kvcount_kernel()
{
    int tb = blockIdx.x >> 2;
    int ng = blockIdx.x & 3;
    int t  = threadIdx.x;              // owns channels 2t, 2t+1
    const unsigned int* qs = (const unsigned int*)g_qs;
    long base = (long)tb * 256 * 768;  // uint units per tb-row: 1536 bf16 = 768 uints
    int c0 = 0, c1 = 0;
#pragma unroll 8
    for (int n = ng * 64; n < ng * 64 + 64; n++) {
        unsigned int k = qs[base + (long)n * 768 + 256 + t];   // k region (ch 512+)
        unsigned int v = qs[base + (long)n * 768 + 512 + t];   // v region (ch 1024+)
        unsigned int a = k & v;
        c0 += (a & 0xFFFFu) ? 1 : 0;
        c1 += (a >> 16)     ? 1 : 0;
    }
    atomicAdd(&g_kvcnt[tb * 512 + 2 * t],     c0);
    atomicAdd(&g_kvcnt[tb * 512 + 2 * t + 1], c1);
}

// talking-heads LIF over counts (vth=0.5)
__global__ void kvlif2_kernel()
{
    int idx = blockIdx.x * 256 + threadIdx.x;   // 8192 = 16 b x 512 c
    int b = idx >> 9, c = idx & 511;
    float v = 0.f;
#pragma unroll
    for (int t = 0; t < TT; t++) {
        int tb = t * BB + b;
        float s = (float)g_kvcnt[tb * 512 + c];
        v = 0.5f * (v + s);
        bool sp = (v >= 0.5f);
        g_kvs[tb * 512 + c] = __float2bfloat16(sp ? 1.f : 0.f);
        if (sp) v = 0.f;
    }
}

// blocks [0,8192): att = q&kv (bitwise, 4 lanes); blocks [8192,16384): vh output
__global__ void attvh_kernel(float4* __restrict__ vh)
{
    int bi = blockIdx.x;
    const uint2* qs2 = (const uint2*)g_qs;
    if (bi < 8192) {
        long i = (long)bi * 256 + threadIdx.x;      // quads over 64*256*512
        int c4 = (int)(i & 127);
        int n  = (int)((i >> 7) & 255);
        int tb = (int)(i >> 15);
        long qq = (((long)tb * 256 + n) * 1536 + c4 * 4) >> 2;   // uint2 index (4 bf16)
        uint2 q = ((uint2*)g_qs)[qq];
        uint2 kv = ((const uint2*)g_kvs)[((long)tb * 512 + c4 * 4) >> 2];
        q.x &= kv.x; q.y &= kv.y;
        ((uint2*)g_qs)[qq] = q;
    } else {
        long i = (long)(bi - 8192) * 256 + threadIdx.x;  // quads over 8,388,608
        int ch4 = (int)(i & 15);
        int n   = (int)((i >> 4) & 255);
        int h   = (int)((i >> 12) & 7);
        int tb  = (int)(i >> 15);
        uint2 s = qs2[(((long)tb * 256 + n) * 1536 + 1024 + h * 64 + ch4 * 4) >> 2];
        float4 o;
        o.x = (s.x & 0xFFFFu)  ? 1.f : 0.f;
        o.y = (s.x >> 16)      ? 1.f : 0.f;
        o.z = (s.y & 0xFFFFu)  ? 1.f : 0.f;
        o.w = (s.y >> 16)      ? 1.f : 0.f;
        vh[i] = o;
    }
}

// ---------------- HMMA GEMM ----------------
// 256 threads, 8 warps (2x4), warp tile 64x32, 3-stage cp.async (K-chunk 32),
// 1 sync/chunk, prefetch depth 2, 2 CTAs/SM.
__global__ void __launch_bounds__(256, 2)
mma_gemm(const __nv_bfloat16* __restrict__ A, long a_bs, int lda,
         const __nv_bfloat16* __restrict__ Whi, const __nv_bfloat16* __restrict__ Wlo,
         long wbase, int K,
         const float* __restrict__ Asc, const float* __restrict__ Bsc,
         const float* __restrict__ Res, long res_bs,
         float* __restrict__ Out, long out_bs, int Mout, int cm)
{
    extern __shared__ char sm[];
    const uint32_t smb = smem_u32(sm);

    const int tid  = threadIdx.x;
    const int lane = tid & 31;
    const int wid  = tid >> 5;          // 8 warps
    const int wm   = wid & 1;           // 2 M-groups of 64 rows
    const int wn   = wid >> 1;          // 4 N-groups of 32 cols
    const int n0   = blockIdx.x * 128;  // spatial
    const int c0   = blockIdx.y * 128;  // channels
    const int tb   = blockIdx.z;
    const int nch  = K >> 5;            // K-chunk = 32; >= 16 always

    const __nv_bfloat16* Ab = A + (long)tb * a_bs + (long)n0 * lda;
    const __nv_bfloat16* Hb = Whi + wbase + (long)c0 * K;
    const __nv_bfloat16* Lb = Wlo + wbase + (long)c0 * K;

    const int arow = (lane & 7) + ((lane >> 3) & 1) * 8;
    const int ac8  = (lane >> 4) * 16;
    const int brow = (lane & 7) + (lane >> 4) * 8;
    const int bc8  = ((lane >> 3) & 1) * 16;

    float acc[4][4][4];
#pragma unroll
    for (int a_ = 0; a_ < 4; a_++)
#pragma unroll
        for (int b_ = 0; b_ < 4; b_++)
#pragma unroll
            for (int r_ = 0; r_ < 4; r_++) acc[a_][b_][r_] = 0.f;

    // per chunk: A 128rx64B, Bhi 128rx64B, Blo 128rx64B; 2 cp16/thread/region
    auto load_stage = [&](int s, int kc) {
        uint32_t base = smb + s * STAGE;
#pragma unroll
        for (int jj = 0; jj < 2; jj++) {
            int u = jj * 256 + tid;            // 0..511
            int r = u >> 2, c16 = u & 3;
            cp16(base + r * RS + c16 * 16, Ab + (long)r * lda + kc * 32 + c16 * 8);
        }
#pragma unroll
        for (int jj = 0; jj < 2; jj++) {
            int u = jj * 256 + tid;
            int r = u >> 2, c16 = u & 3;
            cp16(base + STG_A + r * RS + c16 * 16, Hb + (long)r * K + kc * 32 + c16 * 8);
        }
#pragma unroll
        for (int jj = 0; jj < 2; jj++) {
            int u = jj * 256 + tid;
            int r = u >> 2, c16 = u & 3;
            cp16(base + 2 * STG_A + r * RS + c16 * 16, Lb + (long)r * K + kc * 32 + c16 * 8);
        }
    };

    load_stage(0, 0); CP_COMMIT();
    load_stage(1, 1); CP_COMMIT();

    for (int ch = 0; ch < nch; ch++) {
        if (ch + 1 < nch) { CP_WAIT1(); } else { CP_WAIT0(); }
        __syncthreads();       // loads for ch arrived AND iter ch-1 compute done
        if (ch + 2 < nch) { load_stage((ch + 2) % 3, ch + 2); CP_COMMIT(); }

        const uint32_t ab = smb + (ch % 3) * STAGE;
        const uint32_t hb = ab + STG_A;
        const uint32_t lb = hb + STG_A;

#pragma unroll
        for (int kt = 0; kt < 2; kt++) {
            const int ko = kt * 32;  // byte offset of k16 block
            uint32_t a[4][4];
#pragma unroll
            for (int mt = 0; mt < 4; mt++)
                ldm4(a[mt][0], a[mt][1], a[mt][2], a[mt][3],
                     ab + (wm * 64 + mt * 16 + arow) * RS + ko + ac8);

            uint32_t bh[8], bl[8];
#pragma unroll
            for (int p = 0; p < 2; p++) {
                ldm4(bh[p*4+0], bh[p*4+1], bh[p*4+2], bh[p*4+3],
                     hb + (wn * 32 + p * 16 + brow) * RS + ko + bc8);
                ldm4(bl[p*4+0], bl[p*4+1], bl[p*4+2], bl[p*4+3],
                     lb + (wn * 32 + p * 16 + brow) * RS + ko + bc8);
            }
            // all-hi then all-lo: 16 distinct accumulators per phase, no RAW stalls
#pragma unroll
            for (int g = 0; g < 4; g++) {
                int bi = (g >> 1) * 4 + (g & 1) * 2;
#pragma unroll
                for (int mt = 0; mt < 4; mt++)
                    mma16816(acc[mt][g], a[mt], bh[bi], bh[bi + 1]);
            }
#pragma unroll
            for (int g = 0; g < 4; g++) {
                int bi = (g >> 1) * 4 + (g & 1) * 2;
#pragma unroll
                for (int mt = 0; mt < 4; mt++)
                    mma16816(acc[mt][g], a[mt], bl[bi], bl[bi + 1]);
            }
        }
    }
    __syncthreads();

    // ---------------- epilogue ----------------
    if (!cm) {
#pragma unroll
        for (int mt = 0; mt < 4; mt++) {
#pragma unroll
            for (int g = 0; g < 4; g++) {
                int col = c0 + wn * 32 + g * 8 + (lane & 3) * 2;
                int row = n0 + wm * 64 + mt * 16 + (lane >> 2);
                float sA0 = Asc[col], sA1 = Asc[col + 1];
                float sB0 = Bsc[col], sB1 = Bsc[col + 1];
                float v00 = acc[mt][g][0] * sA0 + sB0;
                float v01 = acc[mt][g][1] * sA1 + sB1;
                float v10 = acc[mt][g][2] * sA0 + sB0;
                float v11 = acc[mt][g][3] * sA1 + sB1;
                if (Res) {
                    const float* r0 = Res + (long)tb * res_bs + (long)row * Mout + col;
                    float2 ra = *(const float2*)r0;
                    float2 rb = *(const float2*)(r0 + 8 * Mout);
                    v00 += ra.x; v01 += ra.y; v10 += rb.x; v11 += rb.y;
                }
                float* o0 = Out + (long)tb * out_bs + (long)row * Mout + col;
                float2 w0; w0.x = v00; w0.y = v01;
                float2 w1; w1.x = v10; w1.y = v11;
                *(float2*)o0 = w0;
                *(float2*)(o0 + 8 * Mout) = w1;
            }
        }
    } else {
        // stage through smem for coalesced channel-major stores
        float* sf = (float*)sm;
#pragma unroll
        for (int mt = 0; mt < 4; mt++) {
#pragma unroll
            for (int g = 0; g < 4; g++) {
                int cl = wn * 32 + g * 8 + (lane & 3) * 2;
                int rl = wm * 64 + mt * 16 + (lane >> 2);
                int col = c0 + cl, row = n0 + rl;
                float sA0 = Asc[col], sA1 = Asc[col + 1];
                float sB0 = Bsc[col], sB1 = Bsc[col + 1];
                float v00 = acc[mt][g][0] * sA0 + sB0;
                float v01 = acc[mt][g][1] * sA1 + sB1;
                float v10 = acc[mt][g][2] * sA0 + sB0;
                float v11 = acc[mt][g][3] * sA1 + sB1;
                const float* r0 = Res + (long)tb * res_bs + (long)row * Mout + col;
                float2 ra = *(const float2*)r0;
                float2 rb = *(const float2*)(r0 + 8 * Mout);
                v00 += ra.x; v01 += ra.y; v10 += rb.x; v11 += rb.y;
                sf[cl * 132 + rl]           = v00;
                sf[(cl + 1) * 132 + rl]     = v01;
                sf[cl * 132 + rl + 8]       = v10;
                sf[(cl + 1) * 132 + rl + 8] = v11;
            }
        }
        __syncthreads();
#pragma unroll
        for (int i = 0; i < 16; i++) {
            int c = wid * 16 + i;
            float* orow = Out + (long)tb * out_bs + (long)(c0 + c) * NN + n0;
#pragma unroll
            for (int j = 0; j < 4; j++)
                orow[lane + j * 32] = sf[c * 132 + lane + j * 32];
        }
    }
}

// ---------------- launch ----------------
extern "C" void kernel_launch(void* const* d_in, const int* in_sizes, int n_in,
                              void* d_out, int out_size)
{
    const float* x      = (const float*)d_in[0];
    const float* q_w    = (const float*)d_in[1];
    const float* k_w    = (const float*)d_in[2];
    const float* v_w    = (const float*)d_in[3];
    const float* proj_w = (const float*)d_in[4];
    const float* proj_b = (const float*)d_in[5];
    const float* fc1_w  = (const float*)d_in[6];
    const float* fc1_b  = (const float*)d_in[7];
    const float* fc2_w  = (const float*)d_in[8];
    const float* fc2_b  = (const float*)d_in[9];
    const float* q_bn   = (const float*)d_in[10];
    const float* k_bn   = (const float*)d_in[11];
    const float* v_bn   = (const float*)d_in[12];
    const float* proj_bn= (const float*)d_in[13];
    const float* fc1_bn = (const float*)d_in[14];
    const float* fc2_bn = (const float*)d_in[15];
    float* out = (float*)d_out;

    cudaFuncSetAttribute(mma_gemm, cudaFuncAttributeMaxDynamicSharedMemorySize, SMEM_TOT);

    float *p_xt, *p_q, *p_xat, *p_h1, *p_A, *p_Bc;
    __nv_bfloat16 *p_sx, *p_qs, *p_h1s, *p_whi, *p_wlo;
    int *p_kvcnt;
    cudaGetSymbolAddress((void**)&p_xt,    g_xt);
    cudaGetSymbolAddress((void**)&p_sx,    g_sx);
    cudaGetSymbolAddress((void**)&p_q,     g_q);
    cudaGetSymbolAddress((void**)&p_qs,    g_qs);
    cudaGetSymbolAddress((void**)&p_xat,   g_xat);
    cudaGetSymbolAddress((void**)&p_h1,    g_h1);
    cudaGetSymbolAddress((void**)&p_h1s,   g_h1s);
    cudaGetSymbolAddress((void**)&p_whi,   g_whi);
    cudaGetSymbolAddress((void**)&p_wlo,   g_wlo);
    cudaGetSymbolAddress((void**)&p_kvcnt, g_kvcnt);
    cudaGetSymbolAddress((void**)&p_A,     g_A);
    cudaGetSymbolAddress((void**)&p_Bc,    g_Bc);

    prep_affine_kernel<<<18, 256>>>(q_bn, k_bn, v_bn, proj_bn, fc1_bn, fc2_bn,
                                    proj_b, fc1_b, fc2_b);
    wconv_kernel<<<12288, 256>>>(q_w, k_w, v_w, proj_w, fc1_w, fc2_w);
    xpose_lif_kernel<<<dim3(8, 16, 16), dim3(32, 8)>>>(x);
    cudaMemsetAsync(p_kvcnt, 0, 64 * 512 * sizeof(int));

    // qkv GEMM (Mout=1536 stacked)
    mma_gemm<<<dim3(2, 12, 64), 256, SMEM_TOT>>>(p_sx, (long)NN*CC, CC,
                                                 p_whi, p_wlo, W_QKV, CC,
                                                 p_A, p_Bc, nullptr, 0,
                                                 p_q, (long)NN*1536, 1536, 0);
    // LIF on qkv (4 elems/thread)
    lif4_kernel<<<6144, 256>>>((const float4*)p_q, (ushort4*)p_qs,
                               BB*NN*1536/4, (long)BB*NN*1536/4, 1.0f);

    // kv counts (coalesced, parallel, exact int atomics) + talking-heads LIF
    kvcount_kernel<<<256, 256>>>();
    kvlif2_kernel<<<32, 256>>>();
    attvh_kernel<<<16384, 256>>>((float4*)(out + (long)TBCN));

    // proj GEMM + BN + identity(x)
    mma_gemm<<<dim3(2, 4, 64), 256, SMEM_TOT>>>(p_qs, (long)NN*1536, 1536,
                                                p_whi, p_wlo, W_PROJ, CC,
                                                p_A + 1536, p_Bc + 1536, p_xt, (long)NN*CC,
                                                p_xat, (long)NN*CC, CC, 0);
    lif4_kernel<<<2048, 256>>>((const float4*)p_xat, (ushort4*)p_sx,
                               BB*NN*CC/4, (long)BB*NN*CC/4, 1.0f);

    // fc1 GEMM
    mma_gemm<<<dim3(2, 16, 64), 256, SMEM_TOT>>>(p_sx, (long)NN*CC, CC,
                                                 p_whi, p_wlo, W_FC1, CC,
                                                 p_A + 2048, p_Bc + 2048, nullptr, 0,
                                                 p_h1, (long)NN*HID, HID, 0);
    lif4_kernel<<<8192, 256>>>((const float4*)p_h1, (ushort4*)p_h1s,
                               BB*NN*HID/4, (long)BB*NN*HID/4, 1.0f);

    // fc2 GEMM + BN + idm(x_attn) -> d_out (channel-major, smem-staged)
    mma_gemm<<<dim3(2, 4, 64), 256, SMEM_TOT>>>(p_h1s, (long)NN*HID, HID,
                                                p_whi, p_wlo, W_FC2, HID,
                                                p_A + 4096, p_Bc + 4096, p_xat, (long)NN*CC,
                                                out, (long)CC*NN, CC, 1);
}

// round 9
// speedup vs baseline: 2.9240x; 1.0966x over previous
#include <cuda_runtime.h>
#include <cuda_bf16.h>
#include <cstdint>

// ---------------- problem constants ----------------
#define TT   4
#define BB   16
#define CC   512
#define NN   256
#define HID  2048
#define TBCN (TT*BB*CC*NN)     // 8,388,608

// ---------------- static scratch ----------------
__device__ float         g_xt  [64L*256*512];    // x transposed, channels-last fp32
__device__ __nv_bfloat16 g_sx  [64L*256*512];    // spikes (x / mlp), bf16
__device__ float         g_q   [64L*256*1536];   // qkv gemm out fp32 (channels-last)
__device__ __nv_bfloat16 g_qs  [64L*256*1536];   // qkv spikes bf16 (att in place in q cols)
__device__ float         g_xat [64L*256*512];    // attention block output fp32
__device__ float         g_h1  [64L*256*2048];   // fc1 out fp32
__device__ __nv_bfloat16 g_h1s [64L*256*2048];   // fc1 spikes bf16
__device__ __nv_bfloat16 g_kvs [64*512];         // kv spikes bf16
__device__ int           g_kvcnt[64*512];        // kv AND-counts (int, exact)
__device__ __nv_bfloat16 g_whi [3145728];        // weights hi bf16: qkv|proj|fc1|fc2
__device__ __nv_bfloat16 g_wlo [3145728];        // weights lo bf16
__device__ float         g_A   [4608];           // folded BN scale
__device__ float         g_Bc  [4608];           // folded BN bias

#define W_QKV  0L
#define W_PROJ 786432L
#define W_FC1  1048576L
#define W_FC2  2097152L

#define BF1 ((unsigned short)0x3F80)

// ---------------- PTX helpers (baseline ISA only) ----------------
__device__ __forceinline__ uint32_t smem_u32(const void* p) {
    uint32_t a;
    asm("{ .reg .u64 t; cvta.to.shared.u64 t, %1; cvt.u32.u64 %0, t; }" : "=r"(a) : "l"(p));
    return a;
}
__device__ __forceinline__ void cp16(uint32_t dst, const void* src) {
    asm volatile("cp.async.cg.shared.global [%0], [%1], 16;" :: "r"(dst), "l"(src));
}
#define CP_COMMIT() asm volatile("cp.async.commit_group;" ::: "memory")
#define CP_WAIT0()  asm volatile("cp.async.wait_group 0;" ::: "memory")

__device__ __forceinline__ void ldm4(uint32_t& r0, uint32_t& r1, uint32_t& r2, uint32_t& r3,
                                     uint32_t addr) {
    asm volatile("ldmatrix.sync.aligned.m8n8.x4.shared.b16 {%0,%1,%2,%3}, [%4];"
                 : "=r"(r0), "=r"(r1), "=r"(r2), "=r"(r3) : "r"(addr));
}
__device__ __forceinline__ void mma16816(float* c, const uint32_t* a, uint32_t b0, uint32_t b1) {
    asm volatile("mma.sync.aligned.m16n8k16.row.col.f32.bf16.bf16.f32 "
                 "{%0,%1,%2,%3}, {%4,%5,%6,%7}, {%8,%9}, {%0,%1,%2,%3};"
                 : "+f"(c[0]), "+f"(c[1]), "+f"(c[2]), "+f"(c[3])
                 : "r"(a[0]), "r"(a[1]), "r"(a[2]), "r"(a[3]), "r"(b0), "r"(b1));
}

// SMEM: per stage A(128x144B) | Bhi(128x144B) | Blo(128x144B); 2 stages; K-chunk 64
#define RS    144
#define STG_A (128*RS)        // 18432
#define STAGE (3*STG_A)       // 55296
#define SMEM_TOT (2*STAGE)    // 110592  (x2 CTAs/SM = 221184 <= 228KB)

// ---------------- prep kernels ----------------
__global__ void prep_affine_kernel(const float* __restrict__ qbn, const float* __restrict__ kbn,
                                   const float* __restrict__ vbn, const float* __restrict__ pbn,
                                   const float* __restrict__ f1bn, const float* __restrict__ f2bn,
                                   const float* __restrict__ pb, const float* __restrict__ f1b,
                                   const float* __restrict__ f2b)
{
    int i = blockIdx.x * blockDim.x + threadIdx.x;
    if (i >= 4608) return;
    const float* bn; int c; int nc; float bias = 0.f;
    if (i < 1536)      { int s = i >> 9; c = i & 511; nc = CC;
                         bn = (s == 0) ? qbn : (s == 1) ? kbn : vbn; }
    else if (i < 2048) { c = i - 1536; nc = CC;  bn = pbn;  bias = pb[c]; }
    else if (i < 4096) { c = i - 2048; nc = HID; bn = f1bn; bias = f1b[c]; }
    else               { c = i - 4096; nc = CC;  bn = f2bn; bias = f2b[c]; }
    float g  = bn[c];
    float be = bn[nc + c];
    float m  = bn[2*nc + c];
    float v  = bn[3*nc + c];
    float a  = g / sqrtf(v + 1e-5f);
    g_A[i]  = a;
    g_Bc[i] = be + (bias - m) * a;
}

__global__ void wconv_kernel(const float* __restrict__ q, const float* __restrict__ k,
                             const float* __restrict__ v, const float* __restrict__ pj,
                             const float* __restrict__ f1, const float* __restrict__ f2)
{
    long i = (long)blockIdx.x * 256 + threadIdx.x;
    if (i >= 3145728L) return;
    float w;
    if (i < 786432L)       { long s = i / 262144L, r = i % 262144L;
                             w = (s == 0) ? q[r] : (s == 1) ? k[r] : v[r]; }
    else if (i < 1048576L) w = pj[i - 786432L];
    else if (i < 2097152L) w = f1[i - 1048576L];
    else                   w = f2[i - 2097152L];
    __nv_bfloat16 h = __float2bfloat16(w);
    g_whi[i] = h;
    g_wlo[i] = __float2bfloat16(w - __bfloat162float(h));
}

// fused transpose + shortcut LIF: x[t,b,c,n] -> g_xt[t,b,n,c] fp32 AND g_sx spikes bf16
__global__ void xpose_lif_kernel(const float* __restrict__ x)
{
    __shared__ float t4[4][32][33];
    int b  = blockIdx.z;
    int n0 = blockIdx.x * 32, c0 = blockIdx.y * 32;
    int tx = threadIdx.x, ty = threadIdx.y;  // (32,8)
#pragma unroll
    for (int t = 0; t < TT; t++)
#pragma unroll
        for (int i = 0; i < 4; i++) {
            int c = c0 + ty + i * 8;
            t4[t][ty + i * 8][tx] = x[(((long)t * BB + b) * CC + c) * NN + n0 + tx];
        }
    __syncthreads();
#pragma unroll
    for (int i = 0; i < 4; i++) {
        int n = n0 + ty + i * 8;
        int c = c0 + tx;
        float v = 0.f;
#pragma unroll
        for (int t = 0; t < TT; t++) {
            float xv = t4[t][tx][ty + i * 8];
            long o = (((long)t * BB + b) * NN + n) * CC + c;
            g_xt[o] = xv;
            v = 0.5f * (v + xv);
            bool sp = (v >= 1.0f);
            g_sx[o] = __float2bfloat16(sp ? 1.f : 0.f);
            if (sp) v = 0.f;
        }
    }
}

// vectorized LIF: 4 elems/thread, fp32 in -> bf16 spikes out
__global__ void lif4_kernel(const float4* __restrict__ in, ushort4* __restrict__ out,
                            int n4, long t4stride, float vth)
{
    int i = blockIdx.x * 256 + threadIdx.x;
    if (i >= n4) return;
    float vx = 0.f, vy = 0.f, vz = 0.f, vw = 0.f;
#pragma unroll
    for (int t = 0; t < TT; t++) {
        float4 xv = in[(long)t * t4stride + i];
        ushort4 s;
        vx = 0.5f * (vx + xv.x); s.x = (vx >= vth) ? BF1 : 0; if (vx >= vth) vx = 0.f;
        vy = 0.5f * (vy + xv.y); s.y = (vy >= vth) ? BF1 : 0; if (vy >= vth) vy = 0.f;
        vz = 0.5f * (vz + xv.z); s.z = (vz >= vth) ? BF1 : 0; if (vz >= vth) vz = 0.f;
        vw = 0.5f * (vw + xv.w); s.w = (vw >= vth) ? BF1 : 0; if (vw >= vth) vw = 0.f;
        out[(long)t * t4stride + i] = s;
    }
}

// coalesced kv AND-count: block = (tb, ngroup of 64 rows); thread owns 2 channels.
__global__ void kvcount_kernel()
{
    int tb = blockIdx.x >> 2;
    int ng = blockIdx.x & 3;
    int t  = threadIdx.x;              // owns channels 2t, 2t+1
    const unsigned int* qs = (const unsigned int*)g_qs;
    long base = (long)tb * 256 * 768;  // uint units per tb-row: 1536 bf16 = 768 uints
    int c0 = 0, c1 = 0;
#pragma unroll 8
    for (int n = ng * 64; n < ng * 64 + 64; n++) {
        unsigned int k = qs[base + (long)n * 768 + 256 + t];
        unsigned int v = qs[base + (long)n * 768 + 512 + t];
        unsigned int a = k & v;
        c0 += (a & 0xFFFFu) ? 1 : 0;
        c1 += (a >> 16)     ? 1 : 0;
    }
    atomicAdd(&g_kvcnt[tb * 512 + 2 * t],     c0);
    atomicAdd(&g_kvcnt[tb * 512 + 2 * t + 1], c1);
}

// talking-heads LIF over counts (vth=0.5)
__global__ void kvlif2_kernel()
{
    int idx = blockIdx.x * 256 + threadIdx.x;   // 8192 = 16 b x 512 c
    int b = idx >> 9, c = idx & 511;
    float v = 0.f;
#pragma unroll
    for (int t = 0; t < TT; t++) {
        int tb = t * BB + b;
        float s = (float)g_kvcnt[tb * 512 + c];
        v = 0.5f * (v + s);
        bool sp = (v >= 0.5f);
        g_kvs[tb * 512 + c] = __float2bfloat16(sp ? 1.f : 0.f);
        if (sp) v = 0.f;
    }
}

// blocks [0,8192): att = q&kv (bitwise, 4 lanes); blocks [8192,16384): vh output
__global__ void attvh_kernel(float4* __restrict__ vh)
{
    int bi = blockIdx.x;
    const uint2* qs2 = (const uint2*)g_qs;
    if (bi < 8192) {
        long i = (long)bi * 256 + threadIdx.x;      // quads over 64*256*512
        int c4 = (int)(i & 127);
        int n  = (int)((i >> 7) & 255);
        int tb = (int)(i >> 15);
        long qq = (((long)tb * 256 + n) * 1536 + c4 * 4) >> 2;   // uint2 index (4 bf16)
        uint2 q = ((uint2*)g_qs)[qq];
        uint2 kv = ((const uint2*)g_kvs)[((long)tb * 512 + c4 * 4) >> 2];
        q.x &= kv.x; q.y &= kv.y;
        ((uint2*)g_qs)[qq] = q;
    } else {
        long i = (long)(bi - 8192) * 256 + threadIdx.x;  // quads over 8,388,608
        int ch4 = (int)(i & 15);
        int n   = (int)((i >> 4) & 255);
        int h   = (int)((i >> 12) & 7);
        int tb  = (int)(i >> 15);
        uint2 s = qs2[(((long)tb * 256 + n) * 1536 + 1024 + h * 64 + ch4 * 4) >> 2];
        float4 o;
        o.x = (s.x & 0xFFFFu)  ? 1.f : 0.f;
        o.y = (s.x >> 16)      ? 1.f : 0.f;
        o.z = (s.y & 0xFFFFu)  ? 1.f : 0.f;
        o.w = (s.y >> 16)      ? 1.f : 0.f;
        vh[i] = o;
    }
}

// ---------------- HMMA GEMM ----------------
// 256 threads, 8 warps (2x4), warp tile 64x32, 2-stage cp.async (K-chunk 64),
// 1 sync/chunk, 2 CTAs/SM.  (best measured config: 139.9us on qkv)
__global__ void __launch_bounds__(256, 2)
mma_gemm(const __nv_bfloat16* __restrict__ A, long a_bs, int lda,
         const __nv_bfloat16* __restrict__ Whi, const __nv_bfloat16* __restrict__ Wlo,
         long wbase, int K,
         const float* __restrict__ Asc, const float* __restrict__ Bsc,
         const float* __restrict__ Res, long res_bs,
         float* __restrict__ Out, long out_bs, int Mout, int cm)
{
    extern __shared__ char sm[];
    const uint32_t smb = smem_u32(sm);

    const int tid  = threadIdx.x;
    const int lane = tid & 31;
    const int wid  = tid >> 5;          // 8 warps
    const int wm   = wid & 1;           // 2 M-groups of 64 rows
    const int wn   = wid >> 1;          // 4 N-groups of 32 cols
    const int n0   = blockIdx.x * 128;  // spatial
    const int c0   = blockIdx.y * 128;  // channels
    const int tb   = blockIdx.z;
    const int nch  = K >> 6;

    const __nv_bfloat16* Ab = A + (long)tb * a_bs + (long)n0 * lda;
    const __nv_bfloat16* Hb = Whi + wbase + (long)c0 * K;
    const __nv_bfloat16* Lb = Wlo + wbase + (long)c0 * K;

    const int arow = (lane & 7) + ((lane >> 3) & 1) * 8;
    const int ac8  = (lane >> 4) * 16;
    const int brow = (lane & 7) + (lane >> 4) * 8;
    const int bc8  = ((lane >> 3) & 1) * 16;

    float acc[4][4][4];
#pragma unroll
    for (int a_ = 0; a_ < 4; a_++)
#pragma unroll
        for (int b_ = 0; b_ < 4; b_++)
#pragma unroll
            for (int r_ = 0; r_ < 4; r_++) acc[a_][b_][r_] = 0.f;

    auto load_stage = [&](int s, int kc) {
        uint32_t base = smb + s * STAGE;
#pragma unroll
        for (int jj = 0; jj < 4; jj++) {
            int u = jj * 256 + tid;            // 0..1023
            int r = u >> 3, c16 = u & 7;
            cp16(base + r * RS + c16 * 16, Ab + (long)r * lda + kc * 64 + c16 * 8);
        }
#pragma unroll
        for (int jj = 0; jj < 4; jj++) {
            int u = jj * 256 + tid;
            int r = u >> 3, c16 = u & 7;
            cp16(base + STG_A + r * RS + c16 * 16, Hb + (long)r * K + kc * 64 + c16 * 8);
        }
#pragma unroll
        for (int jj = 0; jj < 4; jj++) {
            int u = jj * 256 + tid;
            int r = u >> 3, c16 = u & 7;
            cp16(base + 2 * STG_A + r * RS + c16 * 16, Lb + (long)r * K + kc * 64 + c16 * 8);
        }
    };

    load_stage(0, 0);
    CP_COMMIT();

    for (int ch = 0; ch < nch; ch++) {
        CP_WAIT0();            // this thread's loads for chunk ch complete
        __syncthreads();       // all threads' loads done AND iter ch-1 compute done
        if (ch + 1 < nch) { load_stage((ch + 1) & 1, ch + 1); CP_COMMIT(); }

        const int s = ch & 1;
        const uint32_t ab = smb + s * STAGE;
        const uint32_t hb = ab + STG_A;
        const uint32_t lb = hb + STG_A;

#pragma unroll
        for (int kt = 0; kt < 4; kt++) {
            const int ko = kt * 32;  // byte offset of k16 block
            uint32_t a[4][4];
#pragma unroll
            for (int mt = 0; mt < 4; mt++)
                ldm4(a[mt][0], a[mt][1], a[mt][2], a[mt][3],
                     ab + (wm * 64 + mt * 16 + arow) * RS + ko + ac8);

            uint32_t bh[8], bl[8];
#pragma unroll
            for (int p = 0; p < 2; p++) {
                ldm4(bh[p*4+0], bh[p*4+1], bh[p*4+2], bh[p*4+3],
                     hb + (wn * 32 + p * 16 + brow) * RS + ko + bc8);
                ldm4(bl[p*4+0], bl[p*4+1], bl[p*4+2], bl[p*4+3],
                     lb + (wn * 32 + p * 16 + brow) * RS + ko + bc8);
            }
            // all-hi then all-lo: 16 distinct accumulators per phase, no RAW stalls
#pragma unroll
            for (int g = 0; g < 4; g++) {
                int bi = (g >> 1) * 4 + (g & 1) * 2;
#pragma unroll
                for (int mt = 0; mt < 4; mt++)
                    mma16816(acc[mt][g], a[mt], bh[bi], bh[bi + 1]);
            }
#pragma unroll
            for (int g = 0; g < 4; g++) {
                int bi = (g >> 1) * 4 + (g & 1) * 2;
#pragma unroll
                for (int mt = 0; mt < 4; mt++)
                    mma16816(acc[mt][g], a[mt], bl[bi], bl[bi + 1]);
            }
        }
    }
    __syncthreads();

    // ---------------- epilogue ----------------
    if (!cm) {
#pragma unroll
        for (int mt = 0; mt < 4; mt++) {
#pragma unroll
            for (int g = 0; g < 4; g++) {
                int col = c0 + wn * 32 + g * 8 + (lane & 3) * 2;
                int row = n0 + wm * 64 + mt * 16 + (lane >> 2);
                float sA0 = Asc[col], sA1 = Asc[col + 1];
                float sB0 = Bsc[col], sB1 = Bsc[col + 1];
                float v00 = acc[mt][g][0] * sA0 + sB0;
                float v01 = acc[mt][g][1] * sA1 + sB1;
                float v10 = acc[mt][g][2] * sA0 + sB0;
                float v11 = acc[mt][g][3] * sA1 + sB1;
                if (Res) {
                    const float* r0 = Res + (long)tb * res_bs + (long)row * Mout + col;
                    float2 ra = *(const float2*)r0;
                    float2 rb = *(const float2*)(r0 + 8 * Mout);
                    v00 += ra.x; v01 += ra.y; v10 += rb.x; v11 += rb.y;
                }
                float* o0 = Out + (long)tb * out_bs + (long)row * Mout + col;
                float2 w0; w0.x = v00; w0.y = v01;
                float2 w1; w1.x = v10; w1.y = v11;
                *(float2*)o0 = w0;
                *(float2*)(o0 + 8 * Mout) = w1;
            }
        }
    } else {
        // stage through smem for coalesced channel-major stores
        float* sf = (float*)sm;
#pragma unroll
        for (int mt = 0; mt < 4; mt++) {
#pragma unroll
            for (int g = 0; g < 4; g++) {
                int cl = wn * 32 + g * 8 + (lane & 3) * 2;
                int rl = wm * 64 + mt * 16 + (lane >> 2);
                int col = c0 + cl, row = n0 + rl;
                float sA0 = Asc[col], sA1 = Asc[col + 1];
                float sB0 = Bsc[col], sB1 = Bsc[col + 1];
                float v00 = acc[mt][g][0] * sA0 + sB0;
                float v01 = acc[mt][g][1] * sA1 + sB1;
                float v10 = acc[mt][g][2] * sA0 + sB0;
                float v11 = acc[mt][g][3] * sA1 + sB1;
                const float* r0 = Res + (long)tb * res_bs + (long)row * Mout + col;
                float2 ra = *(const float2*)r0;
                float2 rb = *(const float2*)(r0 + 8 * Mout);
                v00 += ra.x; v01 += ra.y; v10 += rb.x; v11 += rb.y;
                sf[cl * 132 + rl]           = v00;
                sf[(cl + 1) * 132 + rl]     = v01;
                sf[cl * 132 + rl + 8]       = v10;
                sf[(cl + 1) * 132 + rl + 8] = v11;
            }
        }
        __syncthreads();
#pragma unroll
        for (int i = 0; i < 16; i++) {
            int c = wid * 16 + i;
            float* orow = Out + (long)tb * out_bs + (long)(c0 + c) * NN + n0;
#pragma unroll
            for (int j = 0; j < 4; j++)
                orow[lane + j * 32] = sf[c * 132 + lane + j * 32];
        }
    }
}

// ---------------- launch ----------------
extern "C" void kernel_launch(void* const* d_in, const int* in_sizes, int n_in,
                              void* d_out, int out_size)
{
    const float* x      = (const float*)d_in[0];
    const float* q_w    = (const float*)d_in[1];
    const float* k_w    = (const float*)d_in[2];
    const float* v_w    = (const float*)d_in[3];
    const float* proj_w = (const float*)d_in[4];
    const float* proj_b = (const float*)d_in[5];
    const float* fc1_w  = (const float*)d_in[6];
    const float* fc1_b  = (const float*)d_in[7];
    const float* fc2_w  = (const float*)d_in[8];
    const float* fc2_b  = (const float*)d_in[9];
    const float* q_bn   = (const float*)d_in[10];
    const float* k_bn   = (const float*)d_in[11];
    const float* v_bn   = (const float*)d_in[12];
    const float* proj_bn= (const float*)d_in[13];
    const float* fc1_bn = (const float*)d_in[14];
    const float* fc2_bn = (const float*)d_in[15];
    float* out = (float*)d_out;

    cudaFuncSetAttribute(mma_gemm, cudaFuncAttributeMaxDynamicSharedMemorySize, SMEM_TOT);

    float *p_xt, *p_q, *p_xat, *p_h1, *p_A, *p_Bc;
    __nv_bfloat16 *p_sx, *p_qs, *p_h1s, *p_whi, *p_wlo;
    int *p_kvcnt;
    cudaGetSymbolAddress((void**)&p_xt,    g_xt);
    cudaGetSymbolAddress((void**)&p_sx,    g_sx);
    cudaGetSymbolAddress((void**)&p_q,     g_q);
    cudaGetSymbolAddress((void**)&p_qs,    g_qs);
    cudaGetSymbolAddress((void**)&p_xat,   g_xat);
    cudaGetSymbolAddress((void**)&p_h1,    g_h1);
    cudaGetSymbolAddress((void**)&p_h1s,   g_h1s);
    cudaGetSymbolAddress((void**)&p_whi,   g_whi);
    cudaGetSymbolAddress((void**)&p_wlo,   g_wlo);
    cudaGetSymbolAddress((void**)&p_kvcnt, g_kvcnt);
    cudaGetSymbolAddress((void**)&p_A,     g_A);
    cudaGetSymbolAddress((void**)&p_Bc,    g_Bc);

    prep_affine_kernel<<<18, 256>>>(q_bn, k_bn, v_bn, proj_bn, fc1_bn, fc2_bn,
                                    proj_b, fc1_b, fc2_b);
    wconv_kernel<<<12288, 256>>>(q_w, k_w, v_w, proj_w, fc1_w, fc2_w);
    xpose_lif_kernel<<<dim3(8, 16, 16), dim3(32, 8)>>>(x);
    cudaMemsetAsync(p_kvcnt, 0, 64 * 512 * sizeof(int));

    // qkv GEMM (Mout=1536 stacked)
    mma_gemm<<<dim3(2, 12, 64), 256, SMEM_TOT>>>(p_sx, (long)NN*CC, CC,
                                                 p_whi, p_wlo, W_QKV, CC,
                                                 p_A, p_Bc, nullptr, 0,
                                                 p_q, (long)NN*1536, 1536, 0);
    // LIF on qkv (4 elems/thread)
    lif4_kernel<<<6144, 256>>>((const float4*)p_q, (ushort4*)p_qs,
                               BB*NN*1536/4, (long)BB*NN*1536/4, 1.0f);

    // kv counts (coalesced, exact int atomics) + talking-heads LIF
    kvcount_kernel<<<256, 256>>>();
    kvlif2_kernel<<<32, 256>>>();
    attvh_kernel<<<16384, 256>>>((float4*)(out + (long)TBCN));

    // proj GEMM + BN + identity(x)
    mma_gemm<<<dim3(2, 4, 64), 256, SMEM_TOT>>>(p_qs, (long)NN*1536, 1536,
                                                p_whi, p_wlo, W_PROJ, CC,
                                                p_A + 1536, p_Bc + 1536, p_xt, (long)NN*CC,
                                                p_xat, (long)NN*CC, CC, 0);
    lif4_kernel<<<2048, 256>>>((const float4*)p_xat, (ushort4*)p_sx,
                               BB*NN*CC/4, (long)BB*NN*CC/4, 1.0f);

    // fc1 GEMM
    mma_gemm<<<dim3(2, 16, 64), 256, SMEM_TOT>>>(p_sx, (long)NN*CC, CC,
                                                 p_whi, p_wlo, W_FC1, CC,
                                                 p_A + 2048, p_Bc + 2048, nullptr, 0,
                                                 p_h1, (long)NN*HID, HID, 0);
    lif4_kernel<<<8192, 256>>>((const float4*)p_h1, (ushort4*)p_h1s,
                               BB*NN*HID/4, (long)BB*NN*HID/4, 1.0f);

    // fc2 GEMM + BN + idm(x_attn) -> d_out (channel-major, smem-staged)
    mma_gemm<<<dim3(2, 4, 64), 256, SMEM_TOT>>>(p_h1s, (long)NN*HID, HID,
                                                p_whi, p_wlo, W_FC2, HID,
                                                p_A + 4096, p_Bc + 4096, p_xat, (long)NN*CC,
                                                out, (long)CC*NN, CC, 1);
}